// round 8
// baseline (speedup 1.0000x reference)
#include <cuda_runtime.h>
#include <math.h>

#define NQ      12
#define DIM     4096          // 2^12
#define NBATCH  4096
#define THREADS 256
#define AMPS    16            // DIM / THREADS amplitudes per thread

typedef unsigned long long ull;

// Packed combined gates: G_q = U3(layer1,q) @ U3(layer0,q), stored as 8
// f32x2 constants per qubit:
//   k=0:(u00r,u00r) 1:(-u00i,u00i) 2:(u01r,u01r) 3:(-u01i,u01i)
//   k=4:(u10r,u10r) 5:(-u10i,u10i) 6:(u11r,u11r) 7:(-u11i,u11i)
// Amp convention: low lane = re, high lane = im.
// Entries [NQ*8 .. NQ*8+3]: column-packed gate for qubit 11 (global bit 0),
// used for the real-input first butterfly: c00=(u00r,u00i) c01 c10 c11.
__device__ __align__(16) ull g_gates2[NQ * 8 + 4];

struct C2 { float r, i; };
__device__ __forceinline__ C2 cmul(C2 a, C2 b) {
    C2 o; o.r = a.r * b.r - a.i * b.i; o.i = a.r * b.i + a.i * b.r; return o;
}
__device__ __forceinline__ C2 cadd(C2 a, C2 b) { C2 o; o.r = a.r + b.r; o.i = a.i + b.i; return o; }

__device__ __forceinline__ ull pack2(float lo, float hi) {
    return (ull)__float_as_uint(lo) | ((ull)__float_as_uint(hi) << 32);
}

// ---------------------------------------------------------------------------
// Prep: build 12 combined 2x2 gates, packed for f32x2 butterflies.
// ---------------------------------------------------------------------------
__global__ void prep_gates_kernel(const float* __restrict__ thetas,
                                  const float* __restrict__ phis,
                                  const float* __restrict__ lams) {
    int q = threadIdx.x;
    if (q >= NQ) return;

    C2 U[2][4];
    #pragma unroll
    for (int l = 0; l < 2; l++) {
        float th = thetas[l * NQ + q];
        float ph = phis[l * NQ + q];
        float la = lams[l * NQ + q];
        float s, c;
        sincosf(th * 0.5f, &s, &c);
        float sl, cl, sp, cp, spl, cpl;
        sincosf(la, &sl, &cl);
        sincosf(ph, &sp, &cp);
        sincosf(ph + la, &spl, &cpl);
        U[l][0] = (C2){c, 0.f};
        U[l][1] = (C2){-cl * s, -sl * s};
        U[l][2] = (C2){cp * s, sp * s};
        U[l][3] = (C2){cpl * c, spl * c};
    }
    C2 G[4];
    G[0] = cadd(cmul(U[1][0], U[0][0]), cmul(U[1][1], U[0][2]));
    G[1] = cadd(cmul(U[1][0], U[0][1]), cmul(U[1][1], U[0][3]));
    G[2] = cadd(cmul(U[1][2], U[0][0]), cmul(U[1][3], U[0][2]));
    G[3] = cadd(cmul(U[1][2], U[0][1]), cmul(U[1][3], U[0][3]));

    ull* g = &g_gates2[q * 8];
    #pragma unroll
    for (int e = 0; e < 4; e++) {
        g[e * 2 + 0] = pack2(G[e].r, G[e].r);
        g[e * 2 + 1] = pack2(-G[e].i, G[e].i);
    }
    if (q == NQ - 1) {   // column-packed copy for the real-input first bit
        g_gates2[NQ * 8 + 0] = pack2(G[0].r, G[0].i);  // c00
        g_gates2[NQ * 8 + 1] = pack2(G[1].r, G[1].i);  // c01
        g_gates2[NQ * 8 + 2] = pack2(G[2].r, G[2].i);  // c10
        g_gates2[NQ * 8 + 3] = pack2(G[3].r, G[3].i);  // c11
    }
}

// ---------------------------------------------------------------------------
// Packed f32x2 helpers
// ---------------------------------------------------------------------------
__device__ __forceinline__ ull f2mul(ull a, ull b) {
    ull d; asm("mul.rn.f32x2 %0, %1, %2;" : "=l"(d) : "l"(a), "l"(b)); return d;
}
__device__ __forceinline__ ull f2fma(ull a, ull b, ull c) {
    ull d; asm("fma.rn.f32x2 %0, %1, %2, %3;" : "=l"(d) : "l"(a), "l"(b), "l"(c)); return d;
}
__device__ __forceinline__ ull swap64(ull x) {   // (re,im) -> (im,re)
    return (x >> 32) | (x << 32);
}
__device__ __forceinline__ ull splat2(float x) { return pack2(x, x); }

struct GateP { ull g00r, g00i, g01r, g01i, g10r, g10i, g11r, g11i; };

// 4x uniform-address LDG.128 (broadcast, L1-hit after first touch).
__device__ __forceinline__ GateP load_gate_g(int bit) {
    const ulonglong2* p = (const ulonglong2*)(g_gates2 + (NQ - 1 - bit) * 8);
    ulonglong2 a = __ldg(p), b = __ldg(p + 1), c = __ldg(p + 2), d = __ldg(p + 3);
    GateP g;
    g.g00r = a.x; g.g00i = a.y; g.g01r = b.x; g.g01i = b.y;
    g.g10r = c.x; g.g10i = c.y; g.g11r = d.x; g.g11i = d.y;
    return g;
}

// Complex 2x2 butterfly, both amplitudes packed f32x2 (re in lane0, im in lane1).
__device__ __forceinline__ void bfly2(ull& x0, ull& x1, const GateP& g) {
    ull q0 = swap64(x0);
    ull q1 = swap64(x1);
    ull y0 = f2mul(g.g00r, x0);
    y0 = f2fma(g.g00i, q0, y0);
    y0 = f2fma(g.g01r, x1, y0);
    y0 = f2fma(g.g01i, q1, y0);
    ull y1 = f2mul(g.g10r, x0);
    y1 = f2fma(g.g10i, q0, y1);
    y1 = f2fma(g.g11r, x1, y1);
    y1 = f2fma(g.g11i, q1, y1);
    x0 = y0; x1 = y1;
}

// Apply one butterfly bit (local bit l) across 16 register amplitudes.
__device__ __forceinline__ void apply_bit(ull a[AMPS], int l, const GateP& g) {
    #pragma unroll
    for (int j = 0; j < AMPS; j++) {
        if (((j >> l) & 1) == 0) bfly2(a[j], a[j | (1 << l)], g);
    }
}

// Ownership map for stage s (base bit b = 4s): thread t, local amp j holds
// global index ((t & ~m) << 4) | (j << b) | (t & m),  m = (1 << b) - 1.
__device__ __forceinline__ int idx_stage(int s, int t, int j) {
    switch (s) {
        case 0: return (t << 4) | j;
        case 1: return ((t >> 4) << 8) | (j << 4) | (t & 15);
        default: return (j << 8) | t;
    }
}

// Bank-conflict-free XOR swizzle (involution) for the 64-bit exchange buffer.
// For all four (stage, rd/wr) patterns, swz(i)&15 is injective over each
// 16-lane phase: stage0 j^lane, stage1 lane^j, stage2 lane^const.
__device__ __forceinline__ int swz(int i) {
    return i ^ ((i >> 4) & 15);
}

// ---------------------------------------------------------------------------
// Main: one CTA per batch row. 16 packed amps per thread; 3 register stages
// of 4 bits each; 2 double-buffered conflict-free smem exchanges.
// ONLY 2 CTA-wide barriers total.
// ---------------------------------------------------------------------------
__global__ __launch_bounds__(THREADS, 3)
void qc_kernel(const float* __restrict__ in, float* __restrict__ out) {
    extern __shared__ ull dbuf[];                 // 2 x 32 KB exchange buffers
    ull* buf0 = dbuf;
    ull* buf1 = dbuf + DIM;
    __shared__ float swarp[THREADS / 32];

    const int t = threadIdx.x;
    const size_t row = (size_t)blockIdx.x * DIM;

    // Load 16 consecutive floats (stage-0 ownership i = t*16 + j).
    float x[AMPS];
    const float4* xin = (const float4*)(in + row);
    float acc = 0.f;
    #pragma unroll
    for (int k = 0; k < 4; k++) {
        float4 v = xin[t * 4 + k];
        x[k * 4 + 0] = v.x; x[k * 4 + 1] = v.y;
        x[k * 4 + 2] = v.z; x[k * 4 + 3] = v.w;
        acc += v.x * v.x + v.y * v.y + v.z * v.z + v.w * v.w;
    }
    // Per-warp partial of ||x||^2; combined per-thread in the epilogue.
    #pragma unroll
    for (int o = 16; o > 0; o >>= 1) acc += __shfl_xor_sync(0xFFFFFFFFu, acc, o);
    if ((t & 31) == 0) swarp[t >> 5] = acc;       // visible after sync #1

    // ---- Stage 0: bits 0..3 ----
    ull a[AMPS];
    {   // bit 0 on REAL inputs, column-packed gates: y = c0*(x0,x0) + c1*(x1,x1)
        const ulonglong2* cp = (const ulonglong2*)(g_gates2 + NQ * 8);
        ulonglong2 cA = __ldg(cp), cB = __ldg(cp + 1);  // c00,c01 / c10,c11
        #pragma unroll
        for (int j = 0; j < AMPS; j += 2) {
            ull s0 = splat2(x[j]);
            ull s1 = splat2(x[j + 1]);
            a[j]     = f2fma(cA.y, s1, f2mul(cA.x, s0));
            a[j + 1] = f2fma(cB.y, s1, f2mul(cB.x, s0));
        }
    }
    { GateP g = load_gate_g(1); apply_bit(a, 1, g); }
    { GateP g = load_gate_g(2); apply_bit(a, 2, g); }
    { GateP g = load_gate_g(3); apply_bit(a, 3, g); }

    // ---- Exchange 0 (buf0): stage-0 -> stage-1 ownership ----
    #pragma unroll
    for (int j = 0; j < AMPS; j++) buf0[swz(idx_stage(0, t, j))] = a[j];
    __syncthreads();                              // barrier #1
    #pragma unroll
    for (int j = 0; j < AMPS; j++) a[j] = buf0[swz(idx_stage(1, t, j))];

    // ---- Stage 1: bits 4..7 ----
    { GateP g = load_gate_g(4); apply_bit(a, 0, g); }
    { GateP g = load_gate_g(5); apply_bit(a, 1, g); }
    { GateP g = load_gate_g(6); apply_bit(a, 2, g); }
    { GateP g = load_gate_g(7); apply_bit(a, 3, g); }

    // ---- Exchange 1 (buf1): stage-1 -> stage-2 ownership (no WAR vs buf0) --
    #pragma unroll
    for (int j = 0; j < AMPS; j++) buf1[swz(idx_stage(1, t, j))] = a[j];
    __syncthreads();                              // barrier #2
    #pragma unroll
    for (int j = 0; j < AMPS; j++) a[j] = buf1[swz(idx_stage(2, t, j))];

    // ---- Stage 2: bits 8..11 ----
    { GateP g = load_gate_g(8);  apply_bit(a, 0, g); }
    { GateP g = load_gate_g(9);  apply_bit(a, 1, g); }
    { GateP g = load_gate_g(10); apply_bit(a, 2, g); }
    { GateP g = load_gate_g(11); apply_bit(a, 3, g); }

    // Epilogue: finish the norm (swarp written before barrier #1), then
    // probabilities. Stage-2 ownership i = (j<<8)|t -> coalesced STG.32.
    float s = 0.f;
    #pragma unroll
    for (int w = 0; w < THREADS / 32; w++) s += swarp[w];
    const float inv = 1.f / s;
    float* o = out + row;
    #pragma unroll
    for (int j = 0; j < AMPS; j++) {
        float re = __uint_as_float((unsigned)(a[j] & 0xFFFFFFFFu));
        float im = __uint_as_float((unsigned)(a[j] >> 32));
        o[(j << 8) | t] = (re * re + im * im) * inv;
    }
}

extern "C" void kernel_launch(void* const* d_in, const int* in_sizes, int n_in,
                              void* d_out, int out_size) {
    const float* inputs = (const float*)d_in[0];   // [4096, 4096]
    const float* thetas = (const float*)d_in[1];   // [2, 12]
    const float* phis   = (const float*)d_in[2];   // [2, 12]
    const float* lams   = (const float*)d_in[3];   // [2, 12]
    float* out = (float*)d_out;

    const int smem_bytes = 2 * DIM * (int)sizeof(ull);   // 64 KB dynamic
    cudaFuncSetAttribute(qc_kernel, cudaFuncAttributeMaxDynamicSharedMemorySize,
                         smem_bytes);

    prep_gates_kernel<<<1, 32>>>(thetas, phis, lams);
    qc_kernel<<<NBATCH, THREADS, smem_bytes>>>(inputs, out);
}

// round 9
// speedup vs baseline: 1.0616x; 1.0616x over previous
#include <cuda_runtime.h>
#include <math.h>

#define NQ      12
#define DIM     4096          // 2^12
#define NBATCH  4096
#define THREADS 256
#define AMPS    16            // DIM / THREADS amplitudes per thread

typedef unsigned long long ull;

// Packed combined gates: G_q = U3(layer1,q) @ U3(layer0,q), stored as 8
// f32x2 constants per qubit:
//   k=0:(u00r,u00r) 1:(-u00i,u00i) 2:(u01r,u01r) 3:(-u01i,u01i)
//   k=4:(u10r,u10r) 5:(-u10i,u10i) 6:(u11r,u11r) 7:(-u11i,u11i)
// Amp convention: low lane = re, high lane = im.
// Entries [NQ*8 .. NQ*8+3]: column-packed gate for qubit 11 (global bit 0),
// used for the real-input first butterfly: c00=(u00r,u00i) c01 c10 c11.
__device__ __align__(16) ull g_gates2[NQ * 8 + 4];

struct C2 { float r, i; };
__device__ __forceinline__ C2 cmul(C2 a, C2 b) {
    C2 o; o.r = a.r * b.r - a.i * b.i; o.i = a.r * b.i + a.i * b.r; return o;
}
__device__ __forceinline__ C2 cadd(C2 a, C2 b) { C2 o; o.r = a.r + b.r; o.i = a.i + b.i; return o; }

__device__ __forceinline__ ull pack2(float lo, float hi) {
    return (ull)__float_as_uint(lo) | ((ull)__float_as_uint(hi) << 32);
}

// ---------------------------------------------------------------------------
// Prep: build 12 combined 2x2 gates, packed for f32x2 butterflies.
// ---------------------------------------------------------------------------
__global__ void prep_gates_kernel(const float* __restrict__ thetas,
                                  const float* __restrict__ phis,
                                  const float* __restrict__ lams) {
    int q = threadIdx.x;
    if (q >= NQ) return;

    C2 U[2][4];
    #pragma unroll
    for (int l = 0; l < 2; l++) {
        float th = thetas[l * NQ + q];
        float ph = phis[l * NQ + q];
        float la = lams[l * NQ + q];
        float s, c;
        sincosf(th * 0.5f, &s, &c);
        float sl, cl, sp, cp, spl, cpl;
        sincosf(la, &sl, &cl);
        sincosf(ph, &sp, &cp);
        sincosf(ph + la, &spl, &cpl);
        U[l][0] = (C2){c, 0.f};
        U[l][1] = (C2){-cl * s, -sl * s};
        U[l][2] = (C2){cp * s, sp * s};
        U[l][3] = (C2){cpl * c, spl * c};
    }
    C2 G[4];
    G[0] = cadd(cmul(U[1][0], U[0][0]), cmul(U[1][1], U[0][2]));
    G[1] = cadd(cmul(U[1][0], U[0][1]), cmul(U[1][1], U[0][3]));
    G[2] = cadd(cmul(U[1][2], U[0][0]), cmul(U[1][3], U[0][2]));
    G[3] = cadd(cmul(U[1][2], U[0][1]), cmul(U[1][3], U[0][3]));

    ull* g = &g_gates2[q * 8];
    #pragma unroll
    for (int e = 0; e < 4; e++) {
        g[e * 2 + 0] = pack2(G[e].r, G[e].r);
        g[e * 2 + 1] = pack2(-G[e].i, G[e].i);
    }
    if (q == NQ - 1) {   // column-packed copy for the real-input first bit
        g_gates2[NQ * 8 + 0] = pack2(G[0].r, G[0].i);  // c00
        g_gates2[NQ * 8 + 1] = pack2(G[1].r, G[1].i);  // c01
        g_gates2[NQ * 8 + 2] = pack2(G[2].r, G[2].i);  // c10
        g_gates2[NQ * 8 + 3] = pack2(G[3].r, G[3].i);  // c11
    }
}

// ---------------------------------------------------------------------------
// Packed f32x2 helpers
// ---------------------------------------------------------------------------
__device__ __forceinline__ ull f2mul(ull a, ull b) {
    ull d; asm("mul.rn.f32x2 %0, %1, %2;" : "=l"(d) : "l"(a), "l"(b)); return d;
}
__device__ __forceinline__ ull f2fma(ull a, ull b, ull c) {
    ull d; asm("fma.rn.f32x2 %0, %1, %2, %3;" : "=l"(d) : "l"(a), "l"(b), "l"(c)); return d;
}
__device__ __forceinline__ ull swap64(ull x) {   // (re,im) -> (im,re)
    return (x >> 32) | (x << 32);
}
__device__ __forceinline__ ull splat2(float x) { return pack2(x, x); }

struct GateP { ull g00r, g00i, g01r, g01i, g10r, g10i, g11r, g11i; };

// 4x LDS.128 gate load from the shared gate table (stages 1-2).
__device__ __forceinline__ GateP load_gate_s(const ull* __restrict__ sg, int bit) {
    const ulonglong2* p = (const ulonglong2*)(sg + (NQ - 1 - bit) * 8);  // bit beta <-> qubit 11-beta
    ulonglong2 a = p[0], b = p[1], c = p[2], d = p[3];
    GateP g;
    g.g00r = a.x; g.g00i = a.y; g.g01r = b.x; g.g01i = b.y;
    g.g10r = c.x; g.g10i = c.y; g.g11r = d.x; g.g11i = d.y;
    return g;
}

// 4x uniform-address LDG.128 from global (stage 0 only, before barrier #1).
__device__ __forceinline__ GateP load_gate_g(int bit) {
    const ulonglong2* p = (const ulonglong2*)(g_gates2 + (NQ - 1 - bit) * 8);
    ulonglong2 a = __ldg(p), b = __ldg(p + 1), c = __ldg(p + 2), d = __ldg(p + 3);
    GateP g;
    g.g00r = a.x; g.g00i = a.y; g.g01r = b.x; g.g01i = b.y;
    g.g10r = c.x; g.g10i = c.y; g.g11r = d.x; g.g11i = d.y;
    return g;
}

// Complex 2x2 butterfly, both amplitudes packed f32x2 (re in lane0, im in lane1).
__device__ __forceinline__ void bfly2(ull& x0, ull& x1, const GateP& g) {
    ull q0 = swap64(x0);
    ull q1 = swap64(x1);
    ull y0 = f2mul(g.g00r, x0);
    y0 = f2fma(g.g00i, q0, y0);
    y0 = f2fma(g.g01r, x1, y0);
    y0 = f2fma(g.g01i, q1, y0);
    ull y1 = f2mul(g.g10r, x0);
    y1 = f2fma(g.g10i, q0, y1);
    y1 = f2fma(g.g11r, x1, y1);
    y1 = f2fma(g.g11i, q1, y1);
    x0 = y0; x1 = y1;
}

// Apply one butterfly bit (local bit l) across 16 register amplitudes.
__device__ __forceinline__ void apply_bit(ull a[AMPS], int l, const GateP& g) {
    #pragma unroll
    for (int j = 0; j < AMPS; j++) {
        if (((j >> l) & 1) == 0) bfly2(a[j], a[j | (1 << l)], g);
    }
}

// Ownership map for stage s (base bit b = 4s): thread t, local amp j holds
// global index ((t & ~m) << 4) | (j << b) | (t & m),  m = (1 << b) - 1.
__device__ __forceinline__ int idx_stage(int s, int t, int j) {
    switch (s) {
        case 0: return (t << 4) | j;
        case 1: return ((t >> 4) << 8) | (j << 4) | (t & 15);
        default: return (j << 8) | t;
    }
}

// Bank-conflict-free XOR swizzle (involution) for the 64-bit exchange buffer.
// For all four (stage, rd/wr) patterns, swz(i)&15 is injective over each
// 16-lane phase: stage0 j^lane, stage1 lane^j, stage2 lane^const.
__device__ __forceinline__ int swz(int i) {
    return i ^ ((i >> 4) & 15);
}

// ---------------------------------------------------------------------------
// Main: one CTA per batch row. 16 packed amps per thread; 3 register stages
// of 4 bits each; 2 double-buffered conflict-free smem exchanges; stage-0
// gates from global (pre-barrier), stage-1/2 gates from shared (broadcast
// LDS, published by barrier #1). ONLY 2 CTA-wide barriers total.
// ---------------------------------------------------------------------------
__global__ __launch_bounds__(THREADS, 3)
void qc_kernel(const float* __restrict__ in, float* __restrict__ out) {
    extern __shared__ ull dbuf[];                 // 2 x 32 KB exchange buffers
    ull* buf0 = dbuf;
    ull* buf1 = dbuf + DIM;
    __shared__ __align__(16) ull sgp[NQ * 8];     // gate table for stages 1-2
    __shared__ float swarp[THREADS / 32];

    const int t = threadIdx.x;
    const size_t row = (size_t)blockIdx.x * DIM;

    // Stage gate table into smem (visible after barrier #1; used by stages 1-2).
    if (t < NQ * 8) sgp[t] = g_gates2[t];

    // Load 16 consecutive floats (stage-0 ownership i = t*16 + j).
    float x[AMPS];
    const float4* xin = (const float4*)(in + row);
    float acc = 0.f;
    #pragma unroll
    for (int k = 0; k < 4; k++) {
        float4 v = xin[t * 4 + k];
        x[k * 4 + 0] = v.x; x[k * 4 + 1] = v.y;
        x[k * 4 + 2] = v.z; x[k * 4 + 3] = v.w;
        acc += v.x * v.x + v.y * v.y + v.z * v.z + v.w * v.w;
    }
    // Per-warp partial of ||x||^2; combined per-thread in the epilogue.
    #pragma unroll
    for (int o = 16; o > 0; o >>= 1) acc += __shfl_xor_sync(0xFFFFFFFFu, acc, o);
    if ((t & 31) == 0) swarp[t >> 5] = acc;       // visible after barrier #1

    // ---- Stage 0: bits 0..3 (gates via uniform LDG, pre-barrier) ----
    ull a[AMPS];
    {   // bit 0 on REAL inputs, column-packed gates: y = c0*(x0,x0) + c1*(x1,x1)
        const ulonglong2* cp = (const ulonglong2*)(g_gates2 + NQ * 8);
        ulonglong2 cA = __ldg(cp), cB = __ldg(cp + 1);  // c00,c01 / c10,c11
        #pragma unroll
        for (int j = 0; j < AMPS; j += 2) {
            ull s0 = splat2(x[j]);
            ull s1 = splat2(x[j + 1]);
            a[j]     = f2fma(cA.y, s1, f2mul(cA.x, s0));
            a[j + 1] = f2fma(cB.y, s1, f2mul(cB.x, s0));
        }
    }
    { GateP g = load_gate_g(1); apply_bit(a, 1, g); }
    { GateP g = load_gate_g(2); apply_bit(a, 2, g); }
    { GateP g = load_gate_g(3); apply_bit(a, 3, g); }

    // ---- Exchange 0 (buf0): stage-0 -> stage-1 ownership ----
    #pragma unroll
    for (int j = 0; j < AMPS; j++) buf0[swz(idx_stage(0, t, j))] = a[j];
    __syncthreads();                              // barrier #1 (also publishes sgp, swarp)
    #pragma unroll
    for (int j = 0; j < AMPS; j++) a[j] = buf0[swz(idx_stage(1, t, j))];

    // ---- Stage 1: bits 4..7 (gates via broadcast LDS) ----
    { GateP g = load_gate_s(sgp, 4); apply_bit(a, 0, g); }
    { GateP g = load_gate_s(sgp, 5); apply_bit(a, 1, g); }
    { GateP g = load_gate_s(sgp, 6); apply_bit(a, 2, g); }
    { GateP g = load_gate_s(sgp, 7); apply_bit(a, 3, g); }

    // ---- Exchange 1 (buf1): stage-1 -> stage-2 ownership (no WAR vs buf0) --
    #pragma unroll
    for (int j = 0; j < AMPS; j++) buf1[swz(idx_stage(1, t, j))] = a[j];
    __syncthreads();                              // barrier #2
    #pragma unroll
    for (int j = 0; j < AMPS; j++) a[j] = buf1[swz(idx_stage(2, t, j))];

    // ---- Stage 2: bits 8..11 (gates via broadcast LDS) ----
    { GateP g = load_gate_s(sgp, 8);  apply_bit(a, 0, g); }
    { GateP g = load_gate_s(sgp, 9);  apply_bit(a, 1, g); }
    { GateP g = load_gate_s(sgp, 10); apply_bit(a, 2, g); }
    { GateP g = load_gate_s(sgp, 11); apply_bit(a, 3, g); }

    // Epilogue: finish the norm (swarp published at barrier #1), then
    // probabilities. Stage-2 ownership i = (j<<8)|t -> coalesced STG.32.
    float s = 0.f;
    #pragma unroll
    for (int w = 0; w < THREADS / 32; w++) s += swarp[w];
    const float inv = 1.f / s;
    float* o = out + row;
    #pragma unroll
    for (int j = 0; j < AMPS; j++) {
        float re = __uint_as_float((unsigned)(a[j] & 0xFFFFFFFFu));
        float im = __uint_as_float((unsigned)(a[j] >> 32));
        o[(j << 8) | t] = (re * re + im * im) * inv;
    }
}

extern "C" void kernel_launch(void* const* d_in, const int* in_sizes, int n_in,
                              void* d_out, int out_size) {
    const float* inputs = (const float*)d_in[0];   // [4096, 4096]
    const float* thetas = (const float*)d_in[1];   // [2, 12]
    const float* phis   = (const float*)d_in[2];   // [2, 12]
    const float* lams   = (const float*)d_in[3];   // [2, 12]
    float* out = (float*)d_out;

    const int smem_bytes = 2 * DIM * (int)sizeof(ull);   // 64 KB dynamic
    cudaFuncSetAttribute(qc_kernel, cudaFuncAttributeMaxDynamicSharedMemorySize,
                         smem_bytes);

    prep_gates_kernel<<<1, 32>>>(thetas, phis, lams);
    qc_kernel<<<NBATCH, THREADS, smem_bytes>>>(inputs, out);
}